// round 3
// baseline (speedup 1.0000x reference)
#include <cuda_runtime.h>
#include <cuda_bf16.h>

// ---------------------------------------------------------------------------
// LoongSpikeKernel: K[ch,h,l] = 2*Re( sum_n C_disc[h,n] * exp(dtA[h,n]*l) )
// H=512, NS=64 states/h, L=2048, CH=1.
//
// R3: 256 threads/block (4 state-groups x 64 l-lanes), GS=16 states/thread.
//   - z[16] stays in registers (R1 lesson: never let state spill).
//   - rotation constants (rr,rr,-ri,ri) moved to SMEM as float4 -> LDS.128
//     broadcast each k-iter; frees 64 regs -> __launch_bounds__(256,3)
//     -> 3 CTAs/SM (occ 12.4% -> ~37%).
//   - 4 interleaved accumulators break the serial acc chain (R2 lesson:
//     kernel was latency-bound at 2 warps/SMSP).
// ---------------------------------------------------------------------------

#define NS 64   // states per h (M*NST)
#define GS 16   // states per thread
#define KCHUNK 32

// Scratch (device globals; allocation-free rule)
__device__ float2 g_dtA[512 * NS];
__device__ float2 g_C2 [512 * NS];
__device__ float4 g_R64[512 * NS];   // (rr, rr, -ri, ri)

__device__ __forceinline__ void sincos_dr(float x, float* s, float* c) {
    // accurate sin/cos of an f32 value: double Cody-Waite reduction + fast sincos
    double pd = (double)x;
    double k  = rint(pd * 0.15915494309189535);      // x / (2*pi)
    float red = (float)__fma_rn(k, -6.283185307179586, pd);
    __sincosf(red, s, c);
}

__device__ __forceinline__ unsigned long long pack2(float lo, float hi) {
    unsigned long long r;
    asm("mov.b64 %0, {%1, %2};" : "=l"(r)
        : "r"(__float_as_uint(lo)), "r"(__float_as_uint(hi)));
    return r;
}

__device__ __forceinline__ unsigned long long add2(unsigned long long a,
                                                   unsigned long long b) {
    unsigned long long r;
    asm("add.rn.f32x2 %0, %1, %2;" : "=l"(r) : "l"(a), "l"(b));
    return r;
}

__device__ __forceinline__ float low32f(unsigned long long a) {
    unsigned lo, hi;
    asm("mov.b64 {%0, %1}, %2;" : "=r"(lo), "=r"(hi) : "l"(a));
    return __uint_as_float(lo);
}

// acc += z; z = z * r  (complex, packed f32x2: lo=re, hi=im)
// rrp = (rr, rr)   rip = (-ri, ri)
__device__ __forceinline__ void cstep(unsigned long long& z, unsigned long long& acc,
                                      unsigned long long rrp, unsigned long long rip) {
    asm("{\n\t"
        ".reg .b32 zl, zh;\n\t"
        ".reg .b64 sw, u;\n\t"
        "add.rn.f32x2 %1, %1, %0;\n\t"
        "mov.b64 {zl, zh}, %0;\n\t"
        "mov.b64 sw, {zh, zl};\n\t"
        "mul.rn.f32x2 u, sw, %3;\n\t"
        "fma.rn.f32x2 %0, %0, %2, u;\n\t"
        "}\n"
        : "+l"(z), "+l"(acc)
        : "l"(rrp), "l"(rip));
}

// ---------------------------------------------------------------------------
__global__ void loong_pre(const float* __restrict__ C_real,
                          const float* __restrict__ log_dt,
                          const float* __restrict__ log_A_real,
                          const float* __restrict__ A_imag,
                          const float* __restrict__ omega_logit,
                          const float* __restrict__ eta_logit,
                          int H, int NST, int M) {
    const float OMIN = 1e-6f, OMAX = 100.0f, EMIN = 1e-6f, EMAX = 10.0f;
    int idx = blockIdx.x * blockDim.x + threadIdx.x;
    int total = H * M * NST;
    if (idx >= total) return;
    int h = idx / (M * NST);
    int j = idx - h * (M * NST);
    int m = j / NST;
    int n = j - m * NST;

    float dt    = expf(log_dt[h]);
    float omega = OMIN + (OMAX - OMIN) / (1.f + expf(-omega_logit[m]));
    float eta   = EMIN + (EMAX - EMIN) / (1.f + expf(-eta_logit[m]));
    float Are   = -expf(log_A_real[h * NST + n]);
    float Aim   = A_imag[h * NST + n];
    float Afr   = -omega + eta * Are;
    float Afi   = eta * Aim;
    float Cr    = eta * C_real[(h * NST + n) * 2 + 0];   // CH = 1
    float Ci    = eta * C_real[(h * NST + n) * 2 + 1];
    float dtAr  = Afr * dt;
    float dtAi  = Afi * dt;

    // (exp(dtA) - 1) / (A_frac + 1e-8)
    float er = expf(dtAr);
    float s1, c1; sincos_dr(dtAi, &s1, &c1);
    float nr = er * c1 - 1.f;
    float ni = er * s1;
    float dr  = Afr + 1e-8f, di = Afi;
    float inv = 1.f / (dr * dr + di * di);
    float qr  = (nr * dr + ni * di) * inv;
    float qi  = (ni * dr - nr * di) * inv;
    float Cdr = Cr * qr - Ci * qi;
    float Cdi = Cr * qi + Ci * qr;
    if (sqrtf(Afr * Afr + Afi * Afi) < 1e-6f) { Cdr = Cr * dt; Cdi = Ci * dt; }

    g_dtA[idx] = make_float2(dtAr, dtAi);
    g_C2 [idx] = make_float2(2.f * Cdr, 2.f * Cdi);

    // r64 = exp(64 * dtA)   (x64 exact in fp32)
    float e64 = expf(64.f * dtAr);
    float s64, c64; sincos_dr(64.f * dtAi, &s64, &c64);
    float rr = e64 * c64, ri = e64 * s64;
    g_R64[idx] = make_float4(rr, rr, -ri, ri);
}

// ---------------------------------------------------------------------------
__global__ __launch_bounds__(256, 3) void loong_main(float* __restrict__ out, int L) {
    const int h   = blockIdx.x;
    const int tid = threadIdx.x;
    const int g   = tid >> 6;      // state group 0..3
    const int t   = tid & 63;      // l lane 0..63
    const int base = h * NS + g * GS;

    __shared__ float4 sQ[NS];                 // rotation constants
    __shared__ float  sR[KCHUNK][4][64];      // per-k group partials (32 KB)
    if (tid < NS) sQ[tid] = g_R64[h * NS + tid];

    // --- seed 16 states into registers: z = C2 * exp(dtA * t) ---
    unsigned long long z[GS];
    const float tf = (float)t;
#pragma unroll
    for (int i = 0; i < GS; i++) {
        float2 a = g_dtA[base + i];
        float2 c = g_C2 [base + i];
        float er = __expf(a.x * tf);
        float s, co; sincos_dr(a.y * tf, &s, &co);
        float zr = er * co, zi = er * s;
        z[i] = pack2(c.x * zr - c.y * zi, c.x * zi + c.y * zr);
    }
    __syncthreads();

    const int iters = (L + 63) >> 6;
    const long long ob = (long long)h * L;
    const float4* qp = &sQ[g * GS];

    for (int k0 = 0; k0 < iters; k0 += KCHUNK) {
        const int kend = (iters - k0 < KCHUNK) ? (iters - k0) : KCHUNK;
#pragma unroll 1
        for (int k = 0; k < kend; k++) {
            unsigned long long acc0 = 0ull, acc1 = 0ull, acc2 = 0ull, acc3 = 0ull;
#pragma unroll
            for (int i = 0; i < GS; i += 4) {
                float4 q0 = qp[i + 0], q1 = qp[i + 1], q2 = qp[i + 2], q3 = qp[i + 3];
                cstep(z[i + 0], acc0, pack2(q0.x, q0.y), pack2(q0.z, q0.w));
                cstep(z[i + 1], acc1, pack2(q1.x, q1.y), pack2(q1.z, q1.w));
                cstep(z[i + 2], acc2, pack2(q2.x, q2.y), pack2(q2.z, q2.w));
                cstep(z[i + 3], acc3, pack2(q3.x, q3.y), pack2(q3.z, q3.w));
            }
            unsigned long long s = add2(add2(acc0, acc1), add2(acc2, acc3));
            sR[k][g][t] = low32f(s);          // real part
        }
        __syncthreads();
        // coalesced epilogue: sum the 4 group partials
        const int lbeg = k0 << 6;
        const int lend = (k0 + kend) << 6;
        for (int l = lbeg + tid; l < lend && l < L; l += 256) {
            int kk = (l >> 6) - k0, tt = l & 63;
            out[ob + l] = (sR[kk][0][tt] + sR[kk][1][tt])
                        + (sR[kk][2][tt] + sR[kk][3][tt]);
        }
        __syncthreads();
    }
}

// ---------------------------------------------------------------------------
extern "C" void kernel_launch(void* const* d_in, const int* in_sizes, int n_in,
                              void* d_out, int out_size) {
    const float* C_real      = (const float*)d_in[0];
    const float* log_dt      = (const float*)d_in[1];
    const float* log_A_real  = (const float*)d_in[2];
    const float* A_imag      = (const float*)d_in[3];
    const float* omega_logit = (const float*)d_in[4];
    const float* eta_logit   = (const float*)d_in[5];

    int H   = in_sizes[1];               // 512
    int NST = in_sizes[2] / H;           // 32
    int M   = in_sizes[4];               // 2
    int L   = out_size / H;              // 2048 (CH = 1)

    int total = H * M * NST;
    loong_pre<<<(total + 127) / 128, 128>>>(C_real, log_dt, log_A_real, A_imag,
                                            omega_logit, eta_logit, H, NST, M);
    loong_main<<<H, 256>>>((float*)d_out, L);
}

// round 4
// speedup vs baseline: 1.8282x; 1.8282x over previous
#include <cuda_runtime.h>
#include <cuda_bf16.h>

// ---------------------------------------------------------------------------
// LoongSpikeKernel: K[ch,h,l] = 2*Re( sum_n C_disc[h,n] * exp(dtA[h,n]*l) )
// H=512, NS=64 states/h, L=2048, CH=1.
//
// R4: state-pair packing. zr=(zr0,zr1), zi=(zi0,zi1) packed f32x2 across TWO
//     states. Per pair step: add2 + 2*mul2 + 2*fma2 = 5 fma-pipe instrs,
//     zero MOVs (R2 lesson), zero inner-loop LDS (R3 lesson).
//     Constants (rr, ri, -ri per pair) live in registers; ~110 regs ->
//     __launch_bounds__(256,2) -> 2 CTAs/SM. 4 acc chains + 8 pair chains
//     give the ILP that R2 lacked.
// ---------------------------------------------------------------------------

#define NS 64   // states per h (M*NST)
#define GS 16   // states per thread
#define NP 8    // packed pairs per thread
#define KCHUNK 32

typedef unsigned long long ull;

// Scratch (device globals; allocation-free rule)
__device__ float2 g_dtA[512 * NS];
__device__ float2 g_C2 [512 * NS];
__device__ float4 g_R64[512 * NS];   // (rr, rr, -ri, ri)

__device__ __forceinline__ void sincos_dr(float x, float* s, float* c) {
    double pd = (double)x;
    double k  = rint(pd * 0.15915494309189535);      // x / (2*pi)
    float red = (float)__fma_rn(k, -6.283185307179586, pd);
    __sincosf(red, s, c);
}

__device__ __forceinline__ ull pack2(float lo, float hi) {
    ull r;
    asm("mov.b64 %0, {%1, %2};" : "=l"(r)
        : "r"(__float_as_uint(lo)), "r"(__float_as_uint(hi)));
    return r;
}
__device__ __forceinline__ ull add2(ull a, ull b) {
    ull r; asm("add.rn.f32x2 %0, %1, %2;" : "=l"(r) : "l"(a), "l"(b)); return r;
}
__device__ __forceinline__ ull mul2(ull a, ull b) {
    ull r; asm("mul.rn.f32x2 %0, %1, %2;" : "=l"(r) : "l"(a), "l"(b)); return r;
}
__device__ __forceinline__ ull fma2(ull a, ull b, ull c) {
    ull r; asm("fma.rn.f32x2 %0, %1, %2, %3;" : "=l"(r) : "l"(a), "l"(b), "l"(c)); return r;
}
__device__ __forceinline__ float sum2(ull a) {
    unsigned lo, hi;
    asm("mov.b64 {%0, %1}, %2;" : "=r"(lo), "=r"(hi) : "l"(a));
    return __uint_as_float(lo) + __uint_as_float(hi);
}

// ---------------------------------------------------------------------------
__global__ void loong_pre(const float* __restrict__ C_real,
                          const float* __restrict__ log_dt,
                          const float* __restrict__ log_A_real,
                          const float* __restrict__ A_imag,
                          const float* __restrict__ omega_logit,
                          const float* __restrict__ eta_logit,
                          int H, int NST, int M) {
    const float OMIN = 1e-6f, OMAX = 100.0f, EMIN = 1e-6f, EMAX = 10.0f;
    int idx = blockIdx.x * blockDim.x + threadIdx.x;
    int total = H * M * NST;
    if (idx >= total) return;
    int h = idx / (M * NST);
    int j = idx - h * (M * NST);
    int m = j / NST;
    int n = j - m * NST;

    float dt    = expf(log_dt[h]);
    float omega = OMIN + (OMAX - OMIN) / (1.f + expf(-omega_logit[m]));
    float eta   = EMIN + (EMAX - EMIN) / (1.f + expf(-eta_logit[m]));
    float Are   = -expf(log_A_real[h * NST + n]);
    float Aim   = A_imag[h * NST + n];
    float Afr   = -omega + eta * Are;
    float Afi   = eta * Aim;
    float Cr    = eta * C_real[(h * NST + n) * 2 + 0];   // CH = 1
    float Ci    = eta * C_real[(h * NST + n) * 2 + 1];
    float dtAr  = Afr * dt;
    float dtAi  = Afi * dt;

    // (exp(dtA) - 1) / (A_frac + 1e-8)
    float er = expf(dtAr);
    float s1, c1; sincos_dr(dtAi, &s1, &c1);
    float nr = er * c1 - 1.f;
    float ni = er * s1;
    float dr  = Afr + 1e-8f, di = Afi;
    float inv = 1.f / (dr * dr + di * di);
    float qr  = (nr * dr + ni * di) * inv;
    float qi  = (ni * dr - nr * di) * inv;
    float Cdr = Cr * qr - Ci * qi;
    float Cdi = Cr * qi + Ci * qr;
    if (sqrtf(Afr * Afr + Afi * Afi) < 1e-6f) { Cdr = Cr * dt; Cdi = Ci * dt; }

    g_dtA[idx] = make_float2(dtAr, dtAi);
    g_C2 [idx] = make_float2(2.f * Cdr, 2.f * Cdi);

    // r64 = exp(64 * dtA)
    float e64 = expf(64.f * dtAr);
    float s64, c64; sincos_dr(64.f * dtAi, &s64, &c64);
    float rr = e64 * c64, ri = e64 * s64;
    g_R64[idx] = make_float4(rr, rr, -ri, ri);
}

// ---------------------------------------------------------------------------
__global__ __launch_bounds__(256, 2) void loong_main(float* __restrict__ out, int L) {
    const int h   = blockIdx.x;
    const int tid = threadIdx.x;
    const int g   = tid >> 6;      // state group 0..3
    const int t   = tid & 63;      // l lane 0..63
    const int base = h * NS + g * GS;

    // --- seed 16 states, packed as 8 state-pairs ---
    ull zr[NP], zi[NP], rr[NP], ri[NP], nri[NP];
    const float tf = (float)t;
#pragma unroll
    for (int p = 0; p < NP; p++) {
        float wr[2], wi[2];
#pragma unroll
        for (int e = 0; e < 2; e++) {
            int i = base + 2 * p + e;
            float2 a = g_dtA[i];
            float2 c = g_C2 [i];
            float er = __expf(a.x * tf);
            float s, co; sincos_dr(a.y * tf, &s, &co);
            float xr = er * co, xi = er * s;
            wr[e] = c.x * xr - c.y * xi;
            wi[e] = c.x * xi + c.y * xr;
        }
        zr[p] = pack2(wr[0], wr[1]);
        zi[p] = pack2(wi[0], wi[1]);
        float4 qa = g_R64[base + 2 * p + 0];
        float4 qb = g_R64[base + 2 * p + 1];
        rr [p] = pack2(qa.x, qb.x);
        ri [p] = pack2(qa.w, qb.w);
        nri[p] = pack2(qa.z, qb.z);
    }

    __shared__ float sR[KCHUNK][4][64];      // per-k group partials (32 KB)
    const int iters = (L + 63) >> 6;
    const long long ob = (long long)h * L;

    for (int k0 = 0; k0 < iters; k0 += KCHUNK) {
        const int kend = (iters - k0 < KCHUNK) ? (iters - k0) : KCHUNK;
#pragma unroll 1
        for (int k = 0; k < kend; k++) {
            ull a0 = 0ull, a1 = 0ull, a2 = 0ull, a3 = 0ull;
#pragma unroll
            for (int p = 0; p < NP; p += 4) {
                a0 = add2(a0, zr[p + 0]);
                a1 = add2(a1, zr[p + 1]);
                a2 = add2(a2, zr[p + 2]);
                a3 = add2(a3, zr[p + 3]);
#pragma unroll
                for (int q = 0; q < 4; q++) {
                    ull tt = mul2(zr[p + q], rr[p + q]);
                    ull uu = mul2(zr[p + q], ri[p + q]);
                    zr[p + q] = fma2(zi[p + q], nri[p + q], tt);
                    zi[p + q] = fma2(zi[p + q], rr [p + q], uu);
                }
            }
            ull s = add2(add2(a0, a1), add2(a2, a3));
            sR[k][g][t] = sum2(s);           // real-part partial for this group
        }
        __syncthreads();
        // coalesced epilogue: sum the 4 group partials
        const int lbeg = k0 << 6;
        const int lend = (k0 + kend) << 6;
        for (int l = lbeg + tid; l < lend && l < L; l += 256) {
            int kk = (l >> 6) - k0, tt = l & 63;
            out[ob + l] = (sR[kk][0][tt] + sR[kk][1][tt])
                        + (sR[kk][2][tt] + sR[kk][3][tt]);
        }
        __syncthreads();
    }
}

// ---------------------------------------------------------------------------
extern "C" void kernel_launch(void* const* d_in, const int* in_sizes, int n_in,
                              void* d_out, int out_size) {
    const float* C_real      = (const float*)d_in[0];
    const float* log_dt      = (const float*)d_in[1];
    const float* log_A_real  = (const float*)d_in[2];
    const float* A_imag      = (const float*)d_in[3];
    const float* omega_logit = (const float*)d_in[4];
    const float* eta_logit   = (const float*)d_in[5];

    int H   = in_sizes[1];               // 512
    int NST = in_sizes[2] / H;           // 32
    int M   = in_sizes[4];               // 2
    int L   = out_size / H;              // 2048 (CH = 1)

    int total = H * M * NST;
    loong_pre<<<(total + 127) / 128, 128>>>(C_real, log_dt, log_A_real, A_imag,
                                            omega_logit, eta_logit, H, NST, M);
    loong_main<<<H, 256>>>((float*)d_out, L);
}

// round 5
// speedup vs baseline: 2.7916x; 1.5269x over previous
#include <cuda_runtime.h>
#include <cuda_bf16.h>

// ---------------------------------------------------------------------------
// LoongSpikeKernel: K[ch,h,l] = 2*Re( sum_n C_disc[h,n] * exp(dtA[h,n]*l) )
// H=512, NS=64 states/h, L=2048, CH=1.
//
// R5:
//  - R4 discovered the inner loop is at its RF-banking bound (~12us);
//    the excess was FP64 range reduction in the per-thread seed path
//    (DMUL+DRINT+DFMA x 2.1M seeds ~ 10us) and the 1.73-wave tail.
//  - Seeds now use fp32 two-term Cody-Waite (c1=6.28125 exact); pre-kernel
//    keeps DP reduction for the r64 rotation constants (one-off, 65K thr).
//  - Grid (H, 2): each CTA does half the l-range (16 k-iters), seeded at
//    l = t + l0. Finer CTAs -> finer wave quantization.
// ---------------------------------------------------------------------------

#define NS 64   // states per h (M*NST)
#define GS 16   // states per thread
#define NP 8    // packed state-pairs per thread
#define NSPLIT 2
#define KCH 16  // k-iters per CTA (L=2048: 32 total / NSPLIT)

typedef unsigned long long ull;

// Scratch (device globals; allocation-free rule)
__device__ float2 g_dtA[512 * NS];
__device__ float2 g_C2 [512 * NS];
__device__ float4 g_R64[512 * NS];   // (rr, rr, -ri, ri)

// one-off accurate reduction (pre-kernel only)
__device__ __forceinline__ void sincos_dr(float x, float* s, float* c) {
    double pd = (double)x;
    double k  = rint(pd * 0.15915494309189535);
    float red = (float)__fma_rn(k, -6.283185307179586, pd);
    __sincosf(red, s, c);
}

// fp32 two-term Cody-Waite (seed path; |x| up to ~1.1e5, err ~4e-6 rad)
__device__ __forceinline__ void sincos_cw(float x, float* s, float* c) {
    float k = rintf(x * 0.15915494309189535f);
    float r = fmaf(k, -6.28125f, x);
    r = fmaf(k, -1.9353071795864769e-3f, r);
    __sincosf(r, s, c);
}

__device__ __forceinline__ ull pack2(float lo, float hi) {
    ull r;
    asm("mov.b64 %0, {%1, %2};" : "=l"(r)
        : "r"(__float_as_uint(lo)), "r"(__float_as_uint(hi)));
    return r;
}
__device__ __forceinline__ ull add2(ull a, ull b) {
    ull r; asm("add.rn.f32x2 %0, %1, %2;" : "=l"(r) : "l"(a), "l"(b)); return r;
}
__device__ __forceinline__ ull mul2(ull a, ull b) {
    ull r; asm("mul.rn.f32x2 %0, %1, %2;" : "=l"(r) : "l"(a), "l"(b)); return r;
}
__device__ __forceinline__ ull fma2(ull a, ull b, ull c) {
    ull r; asm("fma.rn.f32x2 %0, %1, %2, %3;" : "=l"(r) : "l"(a), "l"(b), "l"(c)); return r;
}
__device__ __forceinline__ float sum2(ull a) {
    unsigned lo, hi;
    asm("mov.b64 {%0, %1}, %2;" : "=r"(lo), "=r"(hi) : "l"(a));
    return __uint_as_float(lo) + __uint_as_float(hi);
}

// ---------------------------------------------------------------------------
__global__ void loong_pre(const float* __restrict__ C_real,
                          const float* __restrict__ log_dt,
                          const float* __restrict__ log_A_real,
                          const float* __restrict__ A_imag,
                          const float* __restrict__ omega_logit,
                          const float* __restrict__ eta_logit,
                          int H, int NST, int M) {
    const float OMIN = 1e-6f, OMAX = 100.0f, EMIN = 1e-6f, EMAX = 10.0f;
    int idx = blockIdx.x * blockDim.x + threadIdx.x;
    int total = H * M * NST;
    if (idx >= total) return;
    int h = idx / (M * NST);
    int j = idx - h * (M * NST);
    int m = j / NST;
    int n = j - m * NST;

    float dt    = expf(log_dt[h]);
    float omega = OMIN + (OMAX - OMIN) / (1.f + expf(-omega_logit[m]));
    float eta   = EMIN + (EMAX - EMIN) / (1.f + expf(-eta_logit[m]));
    float Are   = -expf(log_A_real[h * NST + n]);
    float Aim   = A_imag[h * NST + n];
    float Afr   = -omega + eta * Are;
    float Afi   = eta * Aim;
    float Cr    = eta * C_real[(h * NST + n) * 2 + 0];   // CH = 1
    float Ci    = eta * C_real[(h * NST + n) * 2 + 1];
    float dtAr  = Afr * dt;
    float dtAi  = Afi * dt;

    // (exp(dtA) - 1) / (A_frac + 1e-8)
    float er = expf(dtAr);
    float s1, c1; sincos_dr(dtAi, &s1, &c1);
    float nr = er * c1 - 1.f;
    float ni = er * s1;
    float dr  = Afr + 1e-8f, di = Afi;
    float inv = 1.f / (dr * dr + di * di);
    float qr  = (nr * dr + ni * di) * inv;
    float qi  = (ni * dr - nr * di) * inv;
    float Cdr = Cr * qr - Ci * qi;
    float Cdi = Cr * qi + Ci * qr;
    if (sqrtf(Afr * Afr + Afi * Afi) < 1e-6f) { Cdr = Cr * dt; Cdi = Ci * dt; }

    g_dtA[idx] = make_float2(dtAr, dtAi);
    g_C2 [idx] = make_float2(2.f * Cdr, 2.f * Cdi);

    // r64 = exp(64 * dtA)  (exact x64; DP reduction for the recurrence constant)
    float e64 = expf(64.f * dtAr);
    float s64, c64; sincos_dr(64.f * dtAi, &s64, &c64);
    float rr = e64 * c64, ri = e64 * s64;
    g_R64[idx] = make_float4(rr, rr, -ri, ri);
}

// ---------------------------------------------------------------------------
__global__ __launch_bounds__(256, 2) void loong_main(float* __restrict__ out, int L) {
    const int h    = blockIdx.x;
    const int tid  = threadIdx.x;
    const int g    = tid >> 6;     // state group 0..3
    const int t    = tid & 63;     // l lane 0..63
    const int base = h * NS + g * GS;

    const int iters     = (L + 63) >> 6;                  // total k's
    const int kiter_per = (iters + NSPLIT - 1) / NSPLIT;  // per CTA
    const int k0beg     = blockIdx.y * kiter_per;
    const int kcnt0     = iters - k0beg;
    const int kcnt      = (kcnt0 < kiter_per) ? (kcnt0 < 0 ? 0 : kcnt0) : kiter_per;

    // --- seed 16 states at l = t + 64*k0beg, packed as 8 state-pairs ---
    ull zr[NP], zi[NP], rr[NP], ri[NP], nri[NP];
    const float tf = (float)(t + (k0beg << 6));
#pragma unroll
    for (int p = 0; p < NP; p++) {
        float wr[2], wi[2];
#pragma unroll
        for (int e = 0; e < 2; e++) {
            int i = base + 2 * p + e;
            float2 a = g_dtA[i];
            float2 c = g_C2 [i];
            float er = __expf(a.x * tf);
            float s, co; sincos_cw(a.y * tf, &s, &co);
            float xr = er * co, xi = er * s;
            wr[e] = c.x * xr - c.y * xi;
            wi[e] = c.x * xi + c.y * xr;
        }
        zr[p] = pack2(wr[0], wr[1]);
        zi[p] = pack2(wi[0], wi[1]);
        float4 qa = g_R64[base + 2 * p + 0];
        float4 qb = g_R64[base + 2 * p + 1];
        rr [p] = pack2(qa.x, qb.x);
        ri [p] = pack2(qa.w, qb.w);
        nri[p] = pack2(qa.z, qb.z);
    }

    __shared__ float sR[KCH][4][64];          // per-k group partials (16 KB)
    const long long ob = (long long)h * L;

    for (int kk0 = 0; kk0 < kcnt; kk0 += KCH) {
        const int kend = (kcnt - kk0 < KCH) ? (kcnt - kk0) : KCH;
#pragma unroll 1
        for (int k = 0; k < kend; k++) {
            ull a0 = 0ull, a1 = 0ull, a2 = 0ull, a3 = 0ull;
#pragma unroll
            for (int p = 0; p < NP; p += 4) {
                a0 = add2(a0, zr[p + 0]);
                a1 = add2(a1, zr[p + 1]);
                a2 = add2(a2, zr[p + 2]);
                a3 = add2(a3, zr[p + 3]);
#pragma unroll
                for (int q = 0; q < 4; q++) {
                    ull tt = mul2(zr[p + q], rr[p + q]);
                    ull uu = mul2(zr[p + q], ri[p + q]);
                    zr[p + q] = fma2(zi[p + q], nri[p + q], tt);
                    zi[p + q] = fma2(zi[p + q], rr [p + q], uu);
                }
            }
            ull s = add2(add2(a0, a1), add2(a2, a3));
            sR[k][g][t] = sum2(s);            // real-part partial for this group
        }
        __syncthreads();
        // coalesced epilogue: sum the 4 group partials
        const int lbeg = (k0beg + kk0) << 6;
        const int lend = lbeg + (kend << 6);
        for (int l = lbeg + tid; l < lend && l < L; l += 256) {
            int kk = ((l >> 6) - k0beg) - kk0, tt = l & 63;
            out[ob + l] = (sR[kk][0][tt] + sR[kk][1][tt])
                        + (sR[kk][2][tt] + sR[kk][3][tt]);
        }
        __syncthreads();
    }
}

// ---------------------------------------------------------------------------
extern "C" void kernel_launch(void* const* d_in, const int* in_sizes, int n_in,
                              void* d_out, int out_size) {
    const float* C_real      = (const float*)d_in[0];
    const float* log_dt      = (const float*)d_in[1];
    const float* log_A_real  = (const float*)d_in[2];
    const float* A_imag      = (const float*)d_in[3];
    const float* omega_logit = (const float*)d_in[4];
    const float* eta_logit   = (const float*)d_in[5];

    int H   = in_sizes[1];               // 512
    int NST = in_sizes[2] / H;           // 32
    int M   = in_sizes[4];               // 2
    int L   = out_size / H;              // 2048 (CH = 1)

    int total = H * M * NST;
    loong_pre<<<(total + 127) / 128, 128>>>(C_real, log_dt, log_A_real, A_imag,
                                            omega_logit, eta_logit, H, NST, M);
    dim3 grid(H, NSPLIT);
    loong_main<<<grid, 256>>>((float*)d_out, L);
}

// round 6
// speedup vs baseline: 3.6397x; 1.3038x over previous
#include <cuda_runtime.h>
#include <cuda_bf16.h>

// ---------------------------------------------------------------------------
// LoongSpikeKernel: K[ch,h,l] = 2*Re( sum_n C_disc[h,n] * exp(dtA[h,n]*l) )
// H=512, NS=64 states/h, L=2048, CH=1.
//
// R6: second-order REAL recurrence. We only need Re(z), and s_k = Re(C r^k)
//     obeys s_{k+2} = 2Re(r) s_{k+1} - |r|^2 s_k. Per 2 states per k:
//     add2 + mul2 + fma2 = 3 instrs / ~7 RF-banking cycles (vs complex
//     rotation's 5 instrs / 12 cycles -> R5's 12us loop floor drops to ~7us).
//     k-loop unrolled by 2 so the (A,B) role swap costs zero MOVs.
//     Seeds: complex seed at l0 (fp32 Cody-Waite), s1 = Re(w * r64).
// ---------------------------------------------------------------------------

#define NS 64   // states per h (M*NST)
#define GS 16   // states per thread
#define NP 8    // packed state-pairs per thread
#define NSPLIT 2
#define KCH 16  // k-iters per CTA chunk

typedef unsigned long long ull;

// Scratch (device globals; allocation-free rule)
__device__ float2 g_dtA[512 * NS];
__device__ float2 g_C2 [512 * NS];
__device__ float4 g_R64[512 * NS];   // (rr, ri, 2*rr, -|r64|^2)

// one-off accurate reduction (pre-kernel only)
__device__ __forceinline__ void sincos_dr(float x, float* s, float* c) {
    double pd = (double)x;
    double k  = rint(pd * 0.15915494309189535);
    float red = (float)__fma_rn(k, -6.283185307179586, pd);
    __sincosf(red, s, c);
}

// fp32 two-term Cody-Waite (seed path)
__device__ __forceinline__ void sincos_cw(float x, float* s, float* c) {
    float k = rintf(x * 0.15915494309189535f);
    float r = fmaf(k, -6.28125f, x);
    r = fmaf(k, -1.9353071795864769e-3f, r);
    __sincosf(r, s, c);
}

__device__ __forceinline__ ull pack2(float lo, float hi) {
    ull r;
    asm("mov.b64 %0, {%1, %2};" : "=l"(r)
        : "r"(__float_as_uint(lo)), "r"(__float_as_uint(hi)));
    return r;
}
__device__ __forceinline__ ull add2(ull a, ull b) {
    ull r; asm("add.rn.f32x2 %0, %1, %2;" : "=l"(r) : "l"(a), "l"(b)); return r;
}
__device__ __forceinline__ ull mul2(ull a, ull b) {
    ull r; asm("mul.rn.f32x2 %0, %1, %2;" : "=l"(r) : "l"(a), "l"(b)); return r;
}
__device__ __forceinline__ ull fma2(ull a, ull b, ull c) {
    ull r; asm("fma.rn.f32x2 %0, %1, %2, %3;" : "=l"(r) : "l"(a), "l"(b), "l"(c)); return r;
}
__device__ __forceinline__ float sum2(ull a) {
    unsigned lo, hi;
    asm("mov.b64 {%0, %1}, %2;" : "=r"(lo), "=r"(hi) : "l"(a));
    return __uint_as_float(lo) + __uint_as_float(hi);
}

// ---------------------------------------------------------------------------
__global__ void loong_pre(const float* __restrict__ C_real,
                          const float* __restrict__ log_dt,
                          const float* __restrict__ log_A_real,
                          const float* __restrict__ A_imag,
                          const float* __restrict__ omega_logit,
                          const float* __restrict__ eta_logit,
                          int H, int NST, int M) {
    const float OMIN = 1e-6f, OMAX = 100.0f, EMIN = 1e-6f, EMAX = 10.0f;
    int idx = blockIdx.x * blockDim.x + threadIdx.x;
    int total = H * M * NST;
    if (idx >= total) return;
    int h = idx / (M * NST);
    int j = idx - h * (M * NST);
    int m = j / NST;
    int n = j - m * NST;

    float dt    = expf(log_dt[h]);
    float omega = OMIN + (OMAX - OMIN) / (1.f + expf(-omega_logit[m]));
    float eta   = EMIN + (EMAX - EMIN) / (1.f + expf(-eta_logit[m]));
    float Are   = -expf(log_A_real[h * NST + n]);
    float Aim   = A_imag[h * NST + n];
    float Afr   = -omega + eta * Are;
    float Afi   = eta * Aim;
    float Cr    = eta * C_real[(h * NST + n) * 2 + 0];   // CH = 1
    float Ci    = eta * C_real[(h * NST + n) * 2 + 1];
    float dtAr  = Afr * dt;
    float dtAi  = Afi * dt;

    // (exp(dtA) - 1) / (A_frac + 1e-8)
    float er = expf(dtAr);
    float s1, c1; sincos_dr(dtAi, &s1, &c1);
    float nr = er * c1 - 1.f;
    float ni = er * s1;
    float dr  = Afr + 1e-8f, di = Afi;
    float inv = 1.f / (dr * dr + di * di);
    float qr  = (nr * dr + ni * di) * inv;
    float qi  = (ni * dr - nr * di) * inv;
    float Cdr = Cr * qr - Ci * qi;
    float Cdi = Cr * qi + Ci * qr;
    if (sqrtf(Afr * Afr + Afi * Afi) < 1e-6f) { Cdr = Cr * dt; Cdi = Ci * dt; }

    g_dtA[idx] = make_float2(dtAr, dtAi);
    g_C2 [idx] = make_float2(2.f * Cdr, 2.f * Cdi);

    // r64 = exp(64*dtA); recurrence constants: twoa = 2*Re(r64), negq = -|r64|^2
    float e64 = expf(64.f * dtAr);
    float s64, c64; sincos_dr(64.f * dtAi, &s64, &c64);
    float rr = e64 * c64, ri = e64 * s64;
    float negq = -expf(128.f * dtAr);        // -(e64^2), computed exactly
    g_R64[idx] = make_float4(rr, ri, 2.f * rr, negq);
}

// ---------------------------------------------------------------------------
__global__ __launch_bounds__(256, 2) void loong_main(float* __restrict__ out, int L) {
    const int h    = blockIdx.x;
    const int tid  = threadIdx.x;
    const int g    = tid >> 6;     // state group 0..3
    const int t    = tid & 63;     // l lane 0..63
    const int base = h * NS + g * GS;

    const int iters     = (L + 63) >> 6;                  // total k's (32)
    const int kiter_per = (iters + NSPLIT - 1) / NSPLIT;  // per CTA (16)
    const int k0beg     = blockIdx.y * kiter_per;
    const int kcnt0     = iters - k0beg;
    const int kcnt      = (kcnt0 < kiter_per) ? (kcnt0 < 0 ? 0 : kcnt0) : kiter_per;

    // --- seed: A = s(l0), B = s(l0+64) for 16 states, packed as 8 pairs ---
    ull A[NP], B[NP], twoa[NP], negq[NP];
    const float tf = (float)(t + (k0beg << 6));
#pragma unroll
    for (int p = 0; p < NP; p++) {
        float s0v[2], s1v[2];
#pragma unroll
        for (int e = 0; e < 2; e++) {
            int i = base + 2 * p + e;
            float2 a = g_dtA[i];
            float2 c = g_C2 [i];
            float4 q = g_R64[i];
            float er = __expf(a.x * tf);
            float s, co; sincos_cw(a.y * tf, &s, &co);
            float xr = er * co, xi = er * s;
            float wr = c.x * xr - c.y * xi;      // Re(C2 * e^{dtA l0})
            float wi = c.x * xi + c.y * xr;
            s0v[e] = wr;
            s1v[e] = wr * q.x - wi * q.y;        // Re(w * r64)
        }
        A[p] = pack2(s0v[0], s0v[1]);
        B[p] = pack2(s1v[0], s1v[1]);
        float4 qa = g_R64[base + 2 * p + 0];
        float4 qb = g_R64[base + 2 * p + 1];
        twoa[p] = pack2(qa.z, qb.z);
        negq[p] = pack2(qa.w, qb.w);
    }

    __shared__ float sR[KCH][4][64];          // per-k group partials (16 KB)
    const long long ob = (long long)h * L;

    for (int kk0 = 0; kk0 < kcnt; kk0 += KCH) {
        const int kend = (kcnt - kk0 < KCH) ? (kcnt - kk0) : KCH;
#pragma unroll 1
        for (int k = 0; k < kend; k += 2) {
            // --- step even: output A, advance A <- twoa*B + negq*A ---
            {
                ull a0 = 0ull, a1 = 0ull, a2 = 0ull, a3 = 0ull;
#pragma unroll
                for (int p = 0; p < NP; p += 4) {
                    a0 = add2(a0, A[p + 0]);
                    a1 = add2(a1, A[p + 1]);
                    a2 = add2(a2, A[p + 2]);
                    a3 = add2(a3, A[p + 3]);
#pragma unroll
                    for (int q = 0; q < 4; q++)
                        A[p + q] = fma2(B[p + q], twoa[p + q],
                                        mul2(A[p + q], negq[p + q]));
                }
                sR[k][g][t] = sum2(add2(add2(a0, a1), add2(a2, a3)));
            }
            // --- step odd: output B, advance B <- twoa*A + negq*B ---
            {
                ull a0 = 0ull, a1 = 0ull, a2 = 0ull, a3 = 0ull;
#pragma unroll
                for (int p = 0; p < NP; p += 4) {
                    a0 = add2(a0, B[p + 0]);
                    a1 = add2(a1, B[p + 1]);
                    a2 = add2(a2, B[p + 2]);
                    a3 = add2(a3, B[p + 3]);
#pragma unroll
                    for (int q = 0; q < 4; q++)
                        B[p + q] = fma2(A[p + q], twoa[p + q],
                                        mul2(B[p + q], negq[p + q]));
                }
                sR[k + 1][g][t] = sum2(add2(add2(a0, a1), add2(a2, a3)));
            }
        }
        __syncthreads();
        // coalesced epilogue: sum the 4 group partials
        const int lbeg = (k0beg + kk0) << 6;
        const int lend = lbeg + (kend << 6);
        for (int l = lbeg + tid; l < lend && l < L; l += 256) {
            int kk = ((l >> 6) - k0beg) - kk0, tt = l & 63;
            out[ob + l] = (sR[kk][0][tt] + sR[kk][1][tt])
                        + (sR[kk][2][tt] + sR[kk][3][tt]);
        }
        __syncthreads();
    }
}

// ---------------------------------------------------------------------------
extern "C" void kernel_launch(void* const* d_in, const int* in_sizes, int n_in,
                              void* d_out, int out_size) {
    const float* C_real      = (const float*)d_in[0];
    const float* log_dt      = (const float*)d_in[1];
    const float* log_A_real  = (const float*)d_in[2];
    const float* A_imag      = (const float*)d_in[3];
    const float* omega_logit = (const float*)d_in[4];
    const float* eta_logit   = (const float*)d_in[5];

    int H   = in_sizes[1];               // 512
    int NST = in_sizes[2] / H;           // 32
    int M   = in_sizes[4];               // 2
    int L   = out_size / H;              // 2048 (CH = 1)

    int total = H * M * NST;
    loong_pre<<<(total + 127) / 128, 128>>>(C_real, log_dt, log_A_real, A_imag,
                                            omega_logit, eta_logit, H, NST, M);
    dim3 grid(H, NSPLIT);
    loong_main<<<grid, 256>>>((float*)d_out, L);
}